// round 11
// baseline (speedup 1.0000x reference)
#include <cuda_runtime.h>
#include <cstdint>

#define EDIM    8
#define NCODES  1024
#define SP      32768          // 32*32*32 spatial per batch
#define THREADS 128
#define TILE    256            // queries per CTA
#define NVEC    262144
#define NZ      (NVEC * EDIM)  // 2,097,152

typedef unsigned long long ull;

// ---- device scratch (no allocations; self-resetting across graph replays) ----
__device__ float    g_partial[4096];   // per-block loss partials
__device__ int      g_used[NCODES];    // set in combine, counted+reset by finalizer
__device__ unsigned g_ticket = 0;      // completion ticket; finalizer resets to 0

// ---- packed f32x2 helpers (Blackwell FFMA2 path, PTX-only) ----
__device__ __forceinline__ ull pack2(float lo, float hi){
    ull d;
    asm("mov.b64 %0, {%1, %2};" : "=l"(d)
        : "r"(__float_as_uint(lo)), "r"(__float_as_uint(hi)));
    return d;
}
__device__ __forceinline__ ull fma2(ull a, ull b, ull c){
    ull d; asm("fma.rn.f32x2 %0, %1, %2, %3;" : "=l"(d) : "l"(a), "l"(b), "l"(c));
    return d;
}
__device__ __forceinline__ ull mul2(ull a, ull b){
    ull d; asm("mul.rn.f32x2 %0, %1, %2;" : "=l"(d) : "l"(a), "l"(b));
    return d;
}
__device__ __forceinline__ ull add2(ull a, ull b){
    ull d; asm("add.rn.f32x2 %0, %1, %2;" : "=l"(d) : "l"(a), "l"(b));
    return d;
}
union U64F2 { ull u; float2 f; };
__device__ __forceinline__ float2 asf2(ull v){ U64F2 x; x.u = v; return x.f; }

// Bit-exact pair distance: d = fma2(dot2, {-2,-2}, add2(ee2, zz2))
// (exact op structure reproduces the reference rounding; do not change)
__device__ __forceinline__ ull pair_dist_r(const ull* __restrict__ e, ull eep,
                                           const ull* __restrict__ zp, ull zzp, ull m2){
    ull a = mul2(zp[0], e[0]);
    a = fma2(zp[1], e[1], a);
    a = fma2(zp[2], e[2], a);
    a = fma2(zp[3], e[3], a);
    a = fma2(zp[4], e[4], a);
    a = fma2(zp[5], e[5], a);
    a = fma2(zp[6], e[6], a);
    a = fma2(zp[7], e[7], a);
    return fma2(a, m2, add2(eep, zzp));
}

// ---- single fused kernel: codes-in-registers search + combine + finalize ----
__global__ __launch_bounds__(THREADS, 4) void vq_fused(
    const float* __restrict__ z,
    const float* __restrict__ emb,
    float* __restrict__ out,
    int nblocks)
{
    __shared__ __align__(16) ull sQ[TILE * 10];   // 8 packed z + zz (+pad), 20KB
    __shared__ __align__(16) ull sP[TILE * 4];    // per-(query,warp) partial, 8KB
    __shared__ float sRed[THREADS / 32];
    __shared__ bool  sLast;

    const int tid  = threadIdx.x;
    const int wid  = tid >> 5;
    const int lane = tid & 31;

    const int qbase = blockIdx.x * TILE;
    const int b  = qbase >> 15;                 // whole tile shares one batch b
    const int s0 = qbase & (SP - 1);
    const float* zb = z + (size_t)b * (EDIM * SP) + s0;

    // ---- load this lane's 8 codes (4 packed pairs) into registers ----
    // code idx = wid*256 + lane*8 + k*2 + sel  (lane-major => tie-break correct)
    const int cbase = wid * 256 + lane * 8;
    ull e[4][EDIM];
    ull eep[4];
    #pragma unroll
    for (int k = 0; k < 4; k++){
        const float* cA = emb + (size_t)(cbase + 2*k) * EDIM;
        const float* cB = cA + EDIM;
        float sa = 0.f, sb = 0.f;
        #pragma unroll
        for (int c = 0; c < EDIM; c++){
            float a = cA[c], bb = cB[c];
            e[k][c] = pack2(a, bb);
            sa = fmaf(a, a, sa);
            sb = fmaf(bb, bb, sb);
        }
        eep[k] = pack2(sa, sb);
    }

    // ---- stage query tile: packed (v,v) per dim ----
    for (int idx = tid; idx < TILE * EDIM; idx += THREADS){
        int c = idx >> 8;            // TILE == 256
        int i = idx & (TILE - 1);
        float v = zb[c * SP + i];
        sQ[i * 10 + c] = pack2(v, v);
    }
    __syncthreads();
    // zz per query (order c=0..7, same as before)
    for (int i = tid; i < TILE; i += THREADS){
        float zz = 0.f;
        #pragma unroll
        for (int c = 0; c < EDIM; c++){
            float v = __uint_as_float((unsigned)(sQ[i * 10 + c] & 0xffffffffu));
            zz = fmaf(v, v, zz);
        }
        sQ[i * 10 + 8] = pack2(zz, zz);
    }
    __syncthreads();

    const ull m2 = pack2(-2.f, -2.f);

    // ---- main loop: each warp scans all tile queries against its 256 codes ----
    for (int i = 0; i < TILE; i++){
        const ulonglong2* q2 = reinterpret_cast<const ulonglong2*>(sQ + i * 10);
        const ulonglong2 q01 = q2[0];
        const ulonglong2 q23 = q2[1];
        const ulonglong2 q45 = q2[2];
        const ulonglong2 q67 = q2[3];
        ull zq[EDIM] = { q01.x, q01.y, q23.x, q23.y, q45.x, q45.y, q67.x, q67.y };
        const ull zz = sQ[i * 10 + 8];

        float2 d0 = asf2(pair_dist_r(e[0], eep[0], zq, zz, m2));
        float2 d1 = asf2(pair_dist_r(e[1], eep[1], zq, zz, m2));
        float2 d2 = asf2(pair_dist_r(e[2], eep[2], zq, zz, m2));
        float2 d3 = asf2(pair_dist_r(e[3], eep[3], zq, zz, m2));

        float pm0 = fminf(d0.x, d0.y);
        float pm1 = fminf(d1.x, d1.y);
        float pm2 = fminf(d2.x, d2.y);
        float pm3 = fminf(d3.x, d3.y);
        float m = fminf(fminf(pm0, pm1), fminf(pm2, pm3));

        // cross-lane min (value only)
        float wm = m;
        #pragma unroll
        for (int off = 16; off > 0; off >>= 1)
            wm = fminf(wm, __shfl_xor_sync(0xffffffffu, wm, off));

        // lowest lane holding the min -> lowest code idx (lane-major layout)
        unsigned ball = __ballot_sync(0xffffffffu, m == wm);
        int wl = __ffs(ball) - 1;
        if (lane == wl){
            int k = (pm0 == m) ? 0 : (pm1 == m) ? 1 : (pm2 == m) ? 2 : 3;
            float2 dk = (k == 0) ? d0 : (k == 1) ? d1 : (k == 2) ? d2 : d3;
            int sel = (dk.y < dk.x) ? 1 : 0;     // tie -> .x (lower idx)
            int ci = cbase + 2 * k + sel;
            sP[i * 4 + wid] = ((ull)(unsigned)ci << 32) | (ull)__float_as_uint(wm);
        }
    }
    __syncthreads();

    // ---- combine: merge 4 warp partials per query, write outputs ----
    float lossLocal = 0.f;
    for (int i = tid; i < TILE; i += THREADS){
        const ulonglong2* p2 = reinterpret_cast<const ulonglong2*>(sP + i * 4);
        const ulonglong2 pa = p2[0];
        const ulonglong2 pb = p2[1];
        float d  = __uint_as_float((unsigned)(pa.x & 0xffffffffu));
        int   bi = (int)(pa.x >> 32);
        float dn = __uint_as_float((unsigned)(pa.y & 0xffffffffu));
        int   in = (int)(pa.y >> 32);
        if (dn < d){ d = dn; bi = in; }          // strict: earlier warp wins ties
        dn = __uint_as_float((unsigned)(pb.x & 0xffffffffu));
        in = (int)(pb.x >> 32);
        if (dn < d){ d = dn; bi = in; }
        dn = __uint_as_float((unsigned)(pb.y & 0xffffffffu));
        in = (int)(pb.y >> 32);
        if (dn < d){ d = dn; bi = in; }

        lossLocal += d;                           // sum((e-z)^2) == dist (R10-validated)

        const float4* e4 = reinterpret_cast<const float4*>(emb + (size_t)bi * EDIM);
        const float4 ea = e4[0];
        const float4 eb = e4[1];
        float* o = out + (size_t)b * (EDIM * SP) + s0 + i;
        o[0 * SP] = ea.x; o[1 * SP] = ea.y; o[2 * SP] = ea.z; o[3 * SP] = ea.w;
        o[4 * SP] = eb.x; o[5 * SP] = eb.y; o[6 * SP] = eb.z; o[7 * SP] = eb.w;

        out[NZ + 2 + qbase + i] = (float)bi;
        g_used[bi] = 1;
    }

    // ---- block-reduce loss -> deterministic per-block partial ----
    #pragma unroll
    for (int o = 16; o > 0; o >>= 1)
        lossLocal += __shfl_down_sync(0xffffffffu, lossLocal, o);
    const int w = tid >> 5;
    if (lane == 0) sRed[w] = lossLocal;
    __syncthreads();
    if (tid == 0){
        float v = 0.f;
        #pragma unroll
        for (int i = 0; i < THREADS / 32; i++) v += sRed[i];
        g_partial[blockIdx.x] = v;
        __threadfence();
        unsigned old = atomicAdd(&g_ticket, 1u);
        sLast = (old == (unsigned)(nblocks - 1));
    }
    __syncthreads();

    // ---- last block finalizes: loss scalar + unique count (self-resetting) ----
    if (sLast){
        __threadfence();
        int cnt = 0;
        for (int i = tid; i < NCODES; i += THREADS){
            cnt += (g_used[i] != 0);
            g_used[i] = 0;                        // reset for next replay
        }
        float s = 0.f;
        for (int i = tid; i < nblocks; i += THREADS) s += g_partial[i];

        #pragma unroll
        for (int o = 16; o > 0; o >>= 1){
            s   += __shfl_down_sync(0xffffffffu, s, o);
            cnt += __shfl_down_sync(0xffffffffu, cnt, o);
        }
        __shared__ float rs[THREADS / 32];
        __shared__ int   rc[THREADS / 32];
        if (lane == 0){ rs[w] = s; rc[w] = cnt; }
        __syncthreads();
        if (tid == 0){
            float total = 0.f; int ctotal = 0;
            #pragma unroll
            for (int i = 0; i < THREADS / 32; i++){ total += rs[i]; ctotal += rc[i]; }
            // loss = beta*mean + mean = 1.25 * sum / NZ
            out[NZ]     = 1.25f * total / (float)NZ;
            out[NZ + 1] = (float)ctotal;
            __threadfence();
            g_ticket = 0;                         // reset for next graph replay
        }
    }
}

extern "C" void kernel_launch(void* const* d_in, const int* in_sizes, int n_in,
                              void* d_out, int out_size)
{
    const float* z   = (const float*)d_in[0];
    const float* emb = (const float*)d_in[1];
    float* out = (float*)d_out;

    const int nblocks = NVEC / TILE;     // 1024
    vq_fused<<<nblocks, THREADS>>>(z, emb, out, nblocks);
}

// round 12
// speedup vs baseline: 1.6456x; 1.6456x over previous
#include <cuda_runtime.h>
#include <cstdint>

#define EDIM    8
#define NCODES  1024
#define HPAIR   256          // pairs per codebook half
#define SP      32768        // 32*32*32 spatial per batch
#define THREADS 128
#define QPT     4            // queries per thread
#define NVEC    262144
#define NZ      (NVEC * EDIM)
#define NCHUNK  512          // query chunks (each served by 2 half-CTAs)

typedef unsigned long long ull;

// ---- device scratch (no allocations; self-resetting across graph replays) ----
__device__ float    g_bd[2 * NVEC];    // best dist per (half, query)  (L2-resident)
__device__ int      g_bi[2 * NVEC];    // best code idx per (half, query)
__device__ float    g_partial[NCHUNK]; // per-chunk loss partials
__device__ int      g_used[NCODES];    // set by merger, counted+reset by finalizer
__device__ unsigned g_ct[NCHUNK];      // per-chunk tickets (merger resets)
__device__ unsigned g_ticket = 0;      // global ticket; finalizer resets

// ---- packed f32x2 helpers (Blackwell FFMA2 path, PTX-only) ----
__device__ __forceinline__ ull pack2(float lo, float hi){
    ull d;
    asm("mov.b64 %0, {%1, %2};" : "=l"(d)
        : "r"(__float_as_uint(lo)), "r"(__float_as_uint(hi)));
    return d;
}
__device__ __forceinline__ ull fma2(ull a, ull b, ull c){
    ull d; asm("fma.rn.f32x2 %0, %1, %2, %3;" : "=l"(d) : "l"(a), "l"(b), "l"(c));
    return d;
}
__device__ __forceinline__ ull mul2(ull a, ull b){
    ull d; asm("mul.rn.f32x2 %0, %1, %2;" : "=l"(d) : "l"(a), "l"(b));
    return d;
}
__device__ __forceinline__ ull add2(ull a, ull b){
    ull d; asm("add.rn.f32x2 %0, %1, %2;" : "=l"(d) : "l"(a), "l"(b));
    return d;
}
union U64F2 { ull u; float2 f; };
__device__ __forceinline__ float2 asf2(ull v){ U64F2 x; x.u = v; return x.f; }

// Bit-exact pair distance: d_pair = fma2(dot2, {-2,-2}, add2(ee2, zz2))
// (this exact op structure reproduces the reference's rounding; do not change)
__device__ __forceinline__ ull pair_dist(const ulonglong2* ep, ull eep,
                                         const ull* zp, ull zzp, ull m2){
    const ulonglong2 e01 = ep[0];
    const ulonglong2 e23 = ep[1];
    const ulonglong2 e45 = ep[2];
    const ulonglong2 e67 = ep[3];
    ull a = mul2(zp[0], e01.x);
    a = fma2(zp[1], e01.y, a);
    a = fma2(zp[2], e23.x, a);
    a = fma2(zp[3], e23.y, a);
    a = fma2(zp[4], e45.x, a);
    a = fma2(zp[5], e45.y, a);
    a = fma2(zp[6], e67.x, a);
    a = fma2(zp[7], e67.y, a);
    return fma2(a, m2, add2(eep, zzp));
}

// ---- one kernel: half-codebook search + chunk-ticket merge + global finalize ----
__global__ __launch_bounds__(THREADS, 5) void vq_main(
    const float* __restrict__ z,
    const float* __restrict__ emb,
    float* __restrict__ out,
    int nctas)
{
    __shared__ __align__(16) float2 sE[HPAIR * EDIM];  // half codebook, 16KB
    __shared__ __align__(16) float  sEE[HPAIR * 2];    // half norms, 2KB
    __shared__ float sRed[THREADS / 32];
    __shared__ bool  sMerge, sLast;

    const int tid   = threadIdx.x;
    const int h     = blockIdx.x & 1;        // codebook half
    const int chunk = blockIdx.x >> 1;       // query chunk
    const int pbase = h * HPAIR;             // first global pair of this half

    // Stage this half's codebook: sE[p*8+c] = (e[2P][c], e[2P+1][c]), P = pbase+p
    for (int i = tid; i < HPAIR * EDIM; i += THREADS){
        int p = i >> 3, c = i & 7;
        int P = pbase + p;
        sE[i] = make_float2(emb[(2*P)*EDIM + c], emb[(2*P+1)*EDIM + c]);
    }
    for (int j = tid; j < HPAIR * 2; j += THREADS){
        int J = 2 * pbase + j;
        float s = 0.f;
        #pragma unroll
        for (int c = 0; c < EDIM; c++){ float e = emb[J*EDIM + c]; s = fmaf(e, e, s); }
        sEE[j] = s;
    }
    __syncthreads();

    const int part = NVEC / QPT;              // 65536
    const int t = chunk * THREADS + tid;

    int nq[QPT];
    ull zp[QPT][EDIM];
    ull zzp[QPT];

    #pragma unroll
    for (int q = 0; q < QPT; q++){
        nq[q] = t + q * part;
        const int b = nq[q] >> 15;
        const int s = nq[q] & (SP - 1);
        const float* zptr = z + (size_t)b * (EDIM * SP) + s;
        float zz = 0.f;
        #pragma unroll
        for (int c = 0; c < EDIM; c++){
            float v = zptr[c * SP];
            zp[q][c] = pack2(v, v);
            zz = fmaf(v, v, zz);
        }
        zzp[q] = pack2(zz, zz);
    }
    const ull m2 = pack2(-2.f, -2.f);

    float best[QPT];
    int   bgp[QPT];                            // winning LOCAL group base pair (even)
    #pragma unroll
    for (int q = 0; q < QPT; q++){ best[q] = 3.4e38f; bgp[q] = 0; }

    // Group of 2 pairs per step; codebook loads amortized over 4 queries.
    for (int p = 0; p < HPAIR; p += 2){
        const ulonglong2* epA = reinterpret_cast<const ulonglong2*>(sE + p * EDIM);
        const ulonglong2* epB = reinterpret_cast<const ulonglong2*>(sE + (p + 1) * EDIM);
        const ulonglong2 eeAB = *reinterpret_cast<const ulonglong2*>(sEE + 2 * p);

        float2 dA0 = asf2(pair_dist(epA, eeAB.x, zp[0], zzp[0], m2));
        float2 dA1 = asf2(pair_dist(epA, eeAB.x, zp[1], zzp[1], m2));
        float2 dA2 = asf2(pair_dist(epA, eeAB.x, zp[2], zzp[2], m2));
        float2 dA3 = asf2(pair_dist(epA, eeAB.x, zp[3], zzp[3], m2));
        float2 dB0 = asf2(pair_dist(epB, eeAB.y, zp[0], zzp[0], m2));
        float2 dB1 = asf2(pair_dist(epB, eeAB.y, zp[1], zzp[1], m2));
        float2 dB2 = asf2(pair_dist(epB, eeAB.y, zp[2], zzp[2], m2));
        float2 dB3 = asf2(pair_dist(epB, eeAB.y, zp[3], zzp[3], m2));

        {
            float gm = fminf(fminf(dA0.x, dA0.y), fminf(dB0.x, dB0.y));
            bool u = gm < best[0]; bgp[0] = u ? p : bgp[0]; best[0] = fminf(best[0], gm);
        }
        {
            float gm = fminf(fminf(dA1.x, dA1.y), fminf(dB1.x, dB1.y));
            bool u = gm < best[1]; bgp[1] = u ? p : bgp[1]; best[1] = fminf(best[1], gm);
        }
        {
            float gm = fminf(fminf(dA2.x, dA2.y), fminf(dB2.x, dB2.y));
            bool u = gm < best[2]; bgp[2] = u ? p : bgp[2]; best[2] = fminf(best[2], gm);
        }
        {
            float gm = fminf(fminf(dA3.x, dA3.y), fminf(dB3.x, dB3.y));
            bool u = gm < best[3]; bgp[3] = u ? p : bgp[3]; best[3] = fminf(best[3], gm);
        }
    }

    // Rescan winning 2-pair group (bit-exact), first-occurrence argmin; store.
    #pragma unroll
    for (int q = 0; q < QPT; q++){
        const int gp = bgp[q];
        float bd = 3.4e38f;
        int bi = 0;
        #pragma unroll
        for (int j = 0; j < 2; j++){
            const int p = gp + j;
            const ulonglong2* ep = reinterpret_cast<const ulonglong2*>(sE + p * EDIM);
            const ull eep = *reinterpret_cast<const ull*>(sEE + 2 * p);
            float2 df = asf2(pair_dist(ep, eep, zp[q], zzp[q], m2));
            if (df.x < bd){ bd = df.x; bi = 2*(pbase + p); }
            if (df.y < bd){ bd = df.y; bi = 2*(pbase + p) + 1; }
        }
        g_bd[h * NVEC + nq[q]] = bd;
        g_bi[h * NVEC + nq[q]] = bi;
    }

    // ---- per-chunk ticket: second CTA of the pair merges this chunk ----
    __threadfence();
    __syncthreads();
    if (tid == 0){
        unsigned old = atomicAdd(&g_ct[chunk], 1u);
        sMerge = (old == 1u);
        if (sMerge) g_ct[chunk] = 0;            // reset for next replay
    }
    __syncthreads();

    float lossLocal = 0.f;
    if (sMerge){
        __threadfence();                        // acquire both halves' writes
        // batch loads for MLP across the thread's 4 queries
        float d0[QPT], d1[QPT];
        int   i0[QPT], i1[QPT];
        #pragma unroll
        for (int q = 0; q < QPT; q++){
            d0[q] = g_bd[nq[q]];
            d1[q] = g_bd[NVEC + nq[q]];
            i0[q] = g_bi[nq[q]];
            i1[q] = g_bi[NVEC + nq[q]];
        }
        #pragma unroll
        for (int q = 0; q < QPT; q++){
            // strict <: half 0 (lower indices) wins ties -> first-occurrence
            const bool take1 = d1[q] < d0[q];
            const float d  = take1 ? d1[q] : d0[q];
            const int   bi = take1 ? i1[q] : i0[q];
            lossLocal += d;                     // sum((e-z)^2) == dist (R10-validated)

            const int b = nq[q] >> 15;
            const int s = nq[q] & (SP - 1);
            const float4* e4 = reinterpret_cast<const float4*>(emb + (size_t)bi * EDIM);
            const float4 ea = e4[0];
            const float4 eb = e4[1];
            float* o = out + (size_t)b * (EDIM * SP) + s;
            o[0 * SP] = ea.x; o[1 * SP] = ea.y; o[2 * SP] = ea.z; o[3 * SP] = ea.w;
            o[4 * SP] = eb.x; o[5 * SP] = eb.y; o[6 * SP] = eb.z; o[7 * SP] = eb.w;

            out[NZ + 2 + nq[q]] = (float)bi;
            g_used[bi] = 1;
        }

        // chunk loss partial (fixed order: warp shuffle + warp sums)
        #pragma unroll
        for (int o = 16; o > 0; o >>= 1)
            lossLocal += __shfl_down_sync(0xffffffffu, lossLocal, o);
        const int lane = tid & 31, w = tid >> 5;
        if (lane == 0) sRed[w] = lossLocal;
        __syncthreads();
        if (tid == 0){
            float v = 0.f;
            #pragma unroll
            for (int i = 0; i < THREADS / 32; i++) v += sRed[i];
            g_partial[chunk] = v;
        }
    }

    // ---- global ticket: last CTA finalizes loss scalar + unique ----
    __threadfence();
    __syncthreads();
    if (tid == 0){
        unsigned old = atomicAdd(&g_ticket, 1u);
        sLast = (old == (unsigned)(nctas - 1));
    }
    __syncthreads();

    if (sLast){
        __threadfence();
        int cnt = 0;
        for (int i = tid; i < NCODES; i += THREADS){
            cnt += (g_used[i] != 0);
            g_used[i] = 0;                      // reset for next replay
        }
        float s = 0.f;
        for (int i = tid; i < NCHUNK; i += THREADS) s += g_partial[i];

        #pragma unroll
        for (int o = 16; o > 0; o >>= 1){
            s   += __shfl_down_sync(0xffffffffu, s, o);
            cnt += __shfl_down_sync(0xffffffffu, cnt, o);
        }
        const int lane = tid & 31, w = tid >> 5;
        __shared__ float rs[THREADS / 32];
        __shared__ int   rc[THREADS / 32];
        if (lane == 0){ rs[w] = s; rc[w] = cnt; }
        __syncthreads();
        if (tid == 0){
            float total = 0.f; int ctotal = 0;
            #pragma unroll
            for (int i = 0; i < THREADS / 32; i++){ total += rs[i]; ctotal += rc[i]; }
            // loss = beta*mean + mean = 1.25 * sum / NZ
            out[NZ]     = 1.25f * total / (float)NZ;
            out[NZ + 1] = (float)ctotal;
            __threadfence();
            g_ticket = 0;                       // reset for next graph replay
        }
    }
}

extern "C" void kernel_launch(void* const* d_in, const int* in_sizes, int n_in,
                              void* d_out, int out_size)
{
    const float* z   = (const float*)d_in[0];
    const float* emb = (const float*)d_in[1];
    float* out = (float*)d_out;

    const int nctas = NCHUNK * 2;     // 1024 CTAs (512 chunks x 2 codebook halves)
    vq_main<<<nctas, THREADS>>>(z, emb, out, nctas);
}